// round 16
// baseline (speedup 1.0000x reference)
#include <cuda_runtime.h>
#include <math.h>

// ---------------------------------------------------------------------------
// Static device scratch (no allocations allowed)
// ---------------------------------------------------------------------------
__device__ float g_x0[256 * 64 * 64];     // x after double inorm        (4 MB)
__device__ float g_g2[256 * 128 * 128];   // guide lv2                   (16 MB)
__device__ float g_kk16[128 * 128 * 4];   // kk map for pac16
__device__ float g_x1[128 * 128 * 128];   // pac16 out / inorm in-place  (8 MB)
__device__ float g_g1[128 * 256 * 256];   // guide lv1                   (32 MB)
__device__ float g_kk20[256 * 256 * 4];   // kk map for pac20
__device__ float g_x2[64 * 256 * 256];    // pac20 out / inorm in-place  (16 MB)

// ---------------------------------------------------------------------------
// Packed f32x2 + cp.async helpers
// ---------------------------------------------------------------------------
typedef unsigned long long u64;

__device__ __forceinline__ u64 pk2(float x, float y) {
    u64 r;
    asm("mov.b64 %0, {%1, %2};" : "=l"(r) : "f"(x), "f"(y));
    return r;
}
__device__ __forceinline__ void fma2(u64& d, u64 a, u64 b) {
    asm("fma.rn.f32x2 %0, %1, %2, %0;" : "+l"(d) : "l"(a), "l"(b));
}
__device__ __forceinline__ float2 up2(u64 v) {
    float lo, hi;
    asm("mov.b64 {%0, %1}, %2;" : "=f"(lo), "=f"(hi) : "l"(v));
    return make_float2(lo, hi);
}

__device__ __forceinline__ unsigned smem_u32(const void* p) {
    return (unsigned)__cvta_generic_to_shared(p);
}
// 4-byte async copy; ok=false -> zero-fill (src-size 0; src pre-clamped valid)
__device__ __forceinline__ void cp4(unsigned dst, const void* src, bool ok) {
    int sz = ok ? 4 : 0;
    asm volatile("cp.async.ca.shared.global [%0], [%1], 4, %2;"
                 :: "r"(dst), "l"(src), "r"(sz) : "memory");
}
#define CP_COMMIT() asm volatile("cp.async.commit_group;" ::: "memory")

// ---------------------------------------------------------------------------
// Fused double (instance-norm + residual):  y = scale*x + shift
// ---------------------------------------------------------------------------
__global__ void inorm2_kernel(const float* x, float* y, int HW) {
    int c = blockIdx.x;
    const float* xc = x + (size_t)c * HW;
    float* yc = y + (size_t)c * HW;

    float s = 0.f, s2 = 0.f;
    for (int i = threadIdx.x; i < HW; i += blockDim.x) {
        float v = xc[i];
        s += v;
        s2 = fmaf(v, v, s2);
    }
    __shared__ float rs[32], rs2[32];
    #pragma unroll
    for (int o = 16; o; o >>= 1) {
        s += __shfl_xor_sync(0xFFFFFFFFu, s, o);
        s2 += __shfl_xor_sync(0xFFFFFFFFu, s2, o);
    }
    int w = threadIdx.x >> 5, l = threadIdx.x & 31;
    if (l == 0) { rs[w] = s; rs2[w] = s2; }
    __syncthreads();
    int nw = blockDim.x >> 5;
    if (w == 0) {
        s = (l < nw) ? rs[l] : 0.f;
        s2 = (l < nw) ? rs2[l] : 0.f;
        #pragma unroll
        for (int o = 16; o; o >>= 1) {
            s += __shfl_xor_sync(0xFFFFFFFFu, s, o);
            s2 += __shfl_xor_sync(0xFFFFFFFFu, s2, o);
        }
        if (l == 0) { rs[0] = s; rs2[0] = s2; }
    }
    __syncthreads();
    float inv = 1.f / (float)HW;
    float m = rs[0] * inv;
    float v = fmaxf(rs2[0] * inv - m * m, 0.f);
    float r1 = rsqrtf(v + 1e-5f);
    float a = 1.f + r1;
    float r2 = rsqrtf(a * a * v + 1e-5f);
    float scale = a * (r2 + 1.f);
    float shift = -(a * r2 + r1) * m;
    for (int i = threadIdx.x; i < HW; i += blockDim.x)
        yc[i] = fmaf(scale, xc[i], shift);
}

// ---------------------------------------------------------------------------
// Direct 3x3 SAME conv — cp.async double-buffered channel pipeline.
// Block = 128 threads (16x8). Each thread: PY x 2 output pixels, OCT channels.
// ---------------------------------------------------------------------------
template <int CC, int OCT, int PY>
__global__ __launch_bounds__(128) void conv3x3_kernel(
    const float* __restrict__ in, const float* __restrict__ w,
    const float* __restrict__ b, float* __restrict__ out,
    int Cin, int Cout, int H, int W)
{
    constexpr int TH = 8 * PY, TW = 32;
    constexpr int XN = (TH + 2) * (TW + 2);
    constexpr int NP = 2 * PY;
    constexpr int NJ = OCT / 2;
    __shared__ float sIn[2][CC][TH + 2][TW + 2];
    __shared__ __align__(16) float sW[2][CC][9][OCT];

    int tx = threadIdx.x, ty = threadIdx.y;       // (16, 8)
    int tid = ty * 16 + tx;
    int x0 = blockIdx.x * TW, y0 = blockIdx.y * TH;
    int oc0 = blockIdx.z * OCT;
    int HW = H * W;

    u64 acc[NP][NJ];
    #pragma unroll
    for (int p = 0; p < NP; p++)
        #pragma unroll
        for (int j = 0; j < NJ; j++) acc[p][j] = 0ull;

    const int nch = Cin / CC;

    auto prefetch = [&](int chunk, int bi) {
        int cc0 = chunk * CC;
        const int NX = CC * XN;
        for (int idx = tid; idx < NX; idx += 128) {
            int c = idx / XN;
            int r = idx % XN;
            int iy = r / (TW + 2), ix = r % (TW + 2);
            int gy = y0 + iy - 1, gx = x0 + ix - 1;
            bool ok = (gy >= 0 && gy < H && gx >= 0 && gx < W);
            int cgy = min(max(gy, 0), H - 1);
            int cgx = min(max(gx, 0), W - 1);
            cp4(smem_u32(&sIn[bi][c][iy][ix]),
                in + (size_t)(cc0 + c) * HW + (size_t)cgy * W + cgx, ok);
        }
        const int NW = CC * 9 * OCT;
        for (int idx = tid; idx < NW; idx += 128) {
            int oc = idx % OCT;
            int rem = idx / OCT;
            int k = rem % 9;
            int c = rem / 9;
            int gco = oc0 + oc;
            bool ok = (gco < Cout);
            int cg = ok ? gco : 0;
            cp4(smem_u32(&sW[bi][c][k][oc]),
                w + ((size_t)cg * Cin + cc0 + c) * 9 + k, ok);
        }
        CP_COMMIT();
    };

    prefetch(0, 0);
    for (int ch = 0; ch < nch; ch++) {
        int bi = ch & 1;
        if (ch + 1 < nch) {
            prefetch(ch + 1, bi ^ 1);
            asm volatile("cp.async.wait_group 1;" ::: "memory");
        } else {
            asm volatile("cp.async.wait_group 0;" ::: "memory");
        }
        __syncthreads();

        #pragma unroll 1
        for (int c = 0; c < CC; c++) {
            u64 rp[PY + 2][4];
            #pragma unroll
            for (int r = 0; r < PY + 2; r++) {
                float2 v0 = *reinterpret_cast<const float2*>(&sIn[bi][c][PY * ty + r][2 * tx]);
                float2 v1 = *reinterpret_cast<const float2*>(&sIn[bi][c][PY * ty + r][2 * tx + 2]);
                rp[r][0] = pk2(v0.x, v0.x);
                rp[r][1] = pk2(v0.y, v0.y);
                rp[r][2] = pk2(v1.x, v1.x);
                rp[r][3] = pk2(v1.y, v1.y);
            }
            #pragma unroll
            for (int o4 = 0; o4 < OCT / 4; o4++) {
                #pragma unroll
                for (int k = 0; k < 9; k++) {
                    ulonglong2 wp = *reinterpret_cast<const ulonglong2*>(&sW[bi][c][k][o4 * 4]);
                    int ky = k / 3, kx = k % 3;
                    #pragma unroll
                    for (int py = 0; py < PY; py++) {
                        #pragma unroll
                        for (int px = 0; px < 2; px++) {
                            int p = py * 2 + px;
                            fma2(acc[p][o4 * 2 + 0], rp[py + ky][px + kx], wp.x);
                            fma2(acc[p][o4 * 2 + 1], rp[py + ky][px + kx], wp.y);
                        }
                    }
                }
            }
        }
        __syncthreads();
    }

    int gx = x0 + 2 * tx;
    #pragma unroll
    for (int j = 0; j < NJ; j++) {
        #pragma unroll
        for (int sub = 0; sub < 2; sub++) {
            int gco = oc0 + 2 * j + sub;
            if (gco >= Cout) continue;
            float bb = b[gco];
            #pragma unroll
            for (int py = 0; py < PY; py++) {
                float2 a0 = up2(acc[py * 2 + 0][j]);
                float2 a1 = up2(acc[py * 2 + 1][j]);
                float e0 = (sub ? a0.y : a0.x) + bb;
                float e1 = (sub ? a1.y : a1.x) + bb;
                int gy = y0 + PY * ty + py;
                *reinterpret_cast<float2*>(&out[(size_t)gco * HW + (size_t)gy * W + gx]) =
                    make_float2(e0, e1);
            }
        }
    }
}

// ---------------------------------------------------------------------------
// PAC kernel map: kk4[y][x][t]; channel-parallel with smem reduction.
// Invalid/boundary terms stored as 0 so the apply kernel is branch-free.
// ---------------------------------------------------------------------------
__global__ __launch_bounds__(256) void kk_kernel(
    const float* __restrict__ g, float* __restrict__ kk4,
    int Cg, int Ho, int Wo)
{
    int tx = threadIdx.x;        // 0..31 (pixel)
    int grp = threadIdx.y;       // 0..7  (channel group)
    int xo = blockIdx.x * 32 + tx;
    int y = blockIdx.y;
    int HW = Ho * Wo;
    bool yodd = (y & 1), xodd = (xo & 1);
    int i0 = yodd ? 0 : 1, i1 = yodd ? 2 : 1;
    int j0 = xodd ? 0 : 1, j1 = xodd ? 2 : 1;
    bool vi1 = yodd && (y < Ho - 1);
    bool vj1 = xodd && (xo < Wo - 1);

    int Ya[2] = { y + i0 - 1, y + i1 - 1 };
    int Xb[2] = { xo + j0 - 1, xo + j1 - 1 };
    bool ib[4];
    int off[4];
    #pragma unroll
    for (int a = 0; a < 2; a++)
        #pragma unroll
        for (int bb = 0; bb < 2; bb++) {
            int t = a * 2 + bb;
            ib[t] = (Ya[a] >= 0 && Ya[a] < Ho && Xb[bb] >= 0 && Xb[bb] < Wo);
            off[t] = Ya[a] * Wo + Xb[bb];
        }
    int base = y * Wo + xo;
    float s0 = 0.f, s1 = 0.f, s2 = 0.f, s3 = 0.f;
    for (int c = grp; c < Cg; c += 8) {
        const float* gc = g + (size_t)c * HW;
        float gv = gc[base];
        float n0 = ib[0] ? gc[off[0]] : 0.f;
        float n1 = ib[1] ? gc[off[1]] : 0.f;
        float n2 = ib[2] ? gc[off[2]] : 0.f;
        float n3 = ib[3] ? gc[off[3]] : 0.f;
        float d;
        d = n0 - gv; s0 = fmaf(d, d, s0);
        d = n1 - gv; s1 = fmaf(d, d, s1);
        d = n2 - gv; s2 = fmaf(d, d, s2);
        d = n3 - gv; s3 = fmaf(d, d, s3);
    }
    __shared__ float4 red[8][32];
    red[grp][tx] = make_float4(s0, s1, s2, s3);
    __syncthreads();
    if (grp == 0) {
        s0 = 0.f; s1 = 0.f; s2 = 0.f; s3 = 0.f;
        #pragma unroll
        for (int gidx = 0; gidx < 8; gidx++) {
            float4 v = red[gidx][tx];
            s0 += v.x; s1 += v.y; s2 += v.z; s3 += v.w;
        }
        float4 r;
        r.x = expf(-0.5f * s0);
        r.y = vj1 ? expf(-0.5f * s1) : 0.f;
        r.z = vi1 ? expf(-0.5f * s2) : 0.f;
        r.w = (vi1 && vj1) ? expf(-0.5f * s3) : 0.f;
        reinterpret_cast<float4*>(kk4)[base] = r;
    }
}

// ---------------------------------------------------------------------------
// PAC transposed conv apply — quad-parity, cp.async double-buffered pipeline,
// kk DEFERRED TO EPILOGUE: inner loop accumulates per-tap partials
//   acc_t[oc] += in_{src(t)} * w[c,t,oc]
// and the epilogue applies out_p = b + sum_{t in p} kk_t * acc_t[oc].
// (Exact reassociation of a channel-invariant scalar; saves 9 MUL + 5 MOV
// per channel per thread.)
// Block = 128 threads (16x8 quads) -> output tile 32x16. Weights (Ci,Co,3,3).
// ---------------------------------------------------------------------------
template <int CC, int OCT>
__global__ __launch_bounds__(128) void pac_kernel(
    const float* __restrict__ x, const float* __restrict__ kk4,
    const float* __restrict__ w, const float* __restrict__ b,
    float* __restrict__ out, int Ci, int Co, int Hin, int Ho)
{
    const int Wo = Ho;
    const int Win = Hin;
    constexpr int QX = 16, QY = 8;
    constexpr int XH = QY + 1, XW = QX + 2;
    constexpr int XN = XH * XW;
    constexpr int NJ = OCT / 2;
    __shared__ float sX[2][CC][XH][XW];
    __shared__ __align__(16) float sW[2][CC][9][OCT];

    int tx = threadIdx.x, ty = threadIdx.y; // (16, 8)
    int tid = ty * 16 + tx;
    int qx0 = blockIdx.x * QX, qy0 = blockIdx.y * QY;
    int oc0 = blockIdx.z * OCT;
    int ox0 = 2 * (qx0 + tx), oy0 = 2 * (qy0 + ty);
    int HWin = Hin * Win;

    // tap t -> destination output pixel: 0=o00 1=o01 2=o10 3=o11
    constexpr int row_of[9] = { 3, 2, 3, 1, 0, 1, 3, 2, 3 };
    // tap t -> source input pixel: 0=in00 1=in01 2=in10 3=in11
    constexpr int src_of[9] = { 0, 0, 1, 0, 0, 1, 2, 2, 3 };

    const float4* kp4 = reinterpret_cast<const float4*>(kk4);
    float4 kq00 = kp4[(size_t)oy0 * Wo + ox0];
    float4 kq01 = kp4[(size_t)oy0 * Wo + ox0 + 1];
    float4 kq10 = kp4[(size_t)(oy0 + 1) * Wo + ox0];
    float4 kq11 = kp4[(size_t)(oy0 + 1) * Wo + ox0 + 1];
    // kk per tap (indexed by tap t = 3*i + j)
    float kv[9];
    kv[0] = kq11.x;  // k00 -> o11
    kv[1] = kq10.x;  // k01 -> o10
    kv[2] = kq11.y;  // k02 -> o11
    kv[3] = kq01.x;  // k10 -> o01
    kv[4] = kq00.x;  // k11 -> o00
    kv[5] = kq01.y;  // k12 -> o01
    kv[6] = kq11.z;  // k20 -> o11
    kv[7] = kq10.z;  // k21 -> o10
    kv[8] = kq11.w;  // k22 -> o11

    u64 acc[9][NJ];  // per-tap partials (kk applied in epilogue)
    #pragma unroll
    for (int t = 0; t < 9; t++)
        #pragma unroll
        for (int j = 0; j < NJ; j++) acc[t][j] = 0ull;

    const int nch = Ci / CC;

    auto prefetch = [&](int chunk, int bi) {
        int cc0 = chunk * CC;
        const int NX = CC * XN;
        for (int idx = tid; idx < NX; idx += 128) {
            int c = idx / XN;
            int r = idx % XN;
            int ih = r / XW, iw = r % XW;
            int gh = qy0 + ih, gw = qx0 + iw;
            bool ok = (gh < Hin && gw < Win);
            int cgh = min(gh, Hin - 1);
            int cgw = min(gw, Win - 1);
            cp4(smem_u32(&sX[bi][c][ih][iw]),
                x + (size_t)(cc0 + c) * HWin + (size_t)cgh * Win + cgw, ok);
        }
        const int NW = CC * 9 * OCT;
        for (int idx = tid; idx < NW; idx += 128) {
            int oc = idx % OCT;
            int rem = idx / OCT;
            int tap = rem % 9;
            int c = rem / 9;
            int gco = oc0 + oc;
            bool ok = (gco < Co);
            int cg = ok ? gco : 0;
            cp4(smem_u32(&sW[bi][c][tap][oc]),
                w + ((size_t)(cc0 + c) * Co + cg) * 9 + tap, ok);
        }
        CP_COMMIT();
    };

    prefetch(0, 0);
    for (int ch = 0; ch < nch; ch++) {
        int bi = ch & 1;
        if (ch + 1 < nch) {
            prefetch(ch + 1, bi ^ 1);
            asm volatile("cp.async.wait_group 1;" ::: "memory");
        } else {
            asm volatile("cp.async.wait_group 0;" ::: "memory");
        }
        __syncthreads();

        #pragma unroll 1
        for (int c = 0; c < CC; c++) {
            float in00 = sX[bi][c][ty][tx],     in01 = sX[bi][c][ty][tx + 1];
            float in10 = sX[bi][c][ty + 1][tx], in11 = sX[bi][c][ty + 1][tx + 1];
            u64 ip[4] = { pk2(in00, in00), pk2(in01, in01),
                          pk2(in10, in10), pk2(in11, in11) };
            #pragma unroll
            for (int o4 = 0; o4 < OCT / 4; o4++) {
                #pragma unroll
                for (int t = 0; t < 9; t++) {
                    ulonglong2 wp = *reinterpret_cast<const ulonglong2*>(&sW[bi][c][t][o4 * 4]);
                    fma2(acc[t][o4 * 2 + 0], ip[src_of[t]], wp.x);
                    fma2(acc[t][o4 * 2 + 1], ip[src_of[t]], wp.y);
                }
            }
        }
        __syncthreads();
    }

    size_t HWo = (size_t)Ho * Wo;
    #pragma unroll
    for (int j = 0; j < NJ; j++) {
        #pragma unroll
        for (int sub = 0; sub < 2; sub++) {
            int gco = oc0 + 2 * j + sub;
            if (gco >= Co) continue;
            float bb = b[gco];
            float o[4] = { bb, bb, bb, bb };
            #pragma unroll
            for (int t = 0; t < 9; t++) {
                float2 ct = up2(acc[t][j]);
                float v = sub ? ct.y : ct.x;
                o[row_of[t]] = fmaf(kv[t], v, o[row_of[t]]);
            }
            *reinterpret_cast<float2*>(&out[(size_t)gco * HWo + (size_t)oy0 * Wo + ox0]) =
                make_float2(o[0], o[1]);
            *reinterpret_cast<float2*>(&out[(size_t)gco * HWo + (size_t)(oy0 + 1) * Wo + ox0]) =
                make_float2(o[2], o[3]);
        }
    }
}

// ---------------------------------------------------------------------------
// Launcher — single stream, proven grids.
// ---------------------------------------------------------------------------
extern "C" void kernel_launch(void* const* d_in, const int* in_sizes, int n_in,
                              void* d_out, int out_size)
{
    (void)in_sizes; (void)n_in; (void)out_size;
    const float* x      = (const float*)d_in[0];
    const float* ef2    = (const float*)d_in[1];
    const float* ef1    = (const float*)d_in[2];
    const float* w_adj2 = (const float*)d_in[3];
    const float* b_adj2 = (const float*)d_in[4];
    const float* w_adj1 = (const float*)d_in[5];
    const float* b_adj1 = (const float*)d_in[6];
    const float* w_p16  = (const float*)d_in[7];
    const float* b_p16  = (const float*)d_in[8];
    const float* w_p20  = (const float*)d_in[9];
    const float* b_p20  = (const float*)d_in[10];
    const float* w_o    = (const float*)d_in[11];
    const float* b_o    = (const float*)d_in[12];
    float* out = (float*)d_out;

    float *px0, *pg2, *pk16, *px1, *pg1, *pk20, *px2;
    cudaGetSymbolAddress((void**)&px0, g_x0);
    cudaGetSymbolAddress((void**)&pg2, g_g2);
    cudaGetSymbolAddress((void**)&pk16, g_kk16);
    cudaGetSymbolAddress((void**)&px1, g_x1);
    cudaGetSymbolAddress((void**)&pg1, g_g1);
    cudaGetSymbolAddress((void**)&pk20, g_kk20);
    cudaGetSymbolAddress((void**)&px2, g_x2);

    dim3 blk(16, 8);
    dim3 kblk(32, 8);

    // x = double inorm+residual (fused analytically)
    inorm2_kernel<<<256, 256>>>(x, px0, 64 * 64);

    // g2 = conv3x3(ef_lv2): 128 -> 256 @ 128x128
    conv3x3_kernel<8, 8, 2><<<dim3(4, 8, 32), blk>>>(ef2, w_adj2, b_adj2, pg2, 128, 256, 128, 128);

    // kk for pac16 (guide channels = 256, Ho = 128)
    kk_kernel<<<dim3(4, 128), kblk>>>(pg2, pk16, 256, 128, 128);

    // pac16: 256 -> 128, out 128x128  (grid 1024)
    pac_kernel<16, 4><<<dim3(4, 8, 32), blk>>>(px0, pk16, w_p16, b_p16, px1, 256, 128, 64, 128);

    // double inorm+res (in place)
    inorm2_kernel<<<128, 256>>>(px1, px1, 128 * 128);

    // g1 = conv3x3(ef_lv1): 64 -> 128 @ 256x256
    conv3x3_kernel<8, 8, 2><<<dim3(8, 16, 16), blk>>>(ef1, w_adj1, b_adj1, pg1, 64, 128, 256, 256);

    // kk for pac20 (guide channels = 128, Ho = 256)
    kk_kernel<<<dim3(8, 256), kblk>>>(pg1, pk20, 128, 256, 256);

    // pac20: 128 -> 64, out 256x256  (grid 2048)
    pac_kernel<16, 4><<<dim3(8, 16, 16), blk>>>(px1, pk20, w_p20, b_p20, px2, 128, 64, 128, 256);

    // double inorm+res (in place)
    inorm2_kernel<<<64, 256>>>(px2, px2, 256 * 256);

    // final conv: 64 -> 3 @ 256x256 straight into d_out
    conv3x3_kernel<4, 4, 1><<<dim3(8, 32, 1), blk>>>(px2, w_o, b_o, out, 64, 3, 256, 256);
}

// round 17
// speedup vs baseline: 1.3687x; 1.3687x over previous
#include <cuda_runtime.h>
#include <math.h>

// ---------------------------------------------------------------------------
// Static device scratch (no allocations allowed)
// ---------------------------------------------------------------------------
__device__ float g_x0[256 * 64 * 64];     // x after double inorm        (4 MB)
__device__ float g_g2[256 * 128 * 128];   // guide lv2                   (16 MB)
__device__ float g_kk16[128 * 128 * 4];   // kk map for pac16
__device__ float g_x1[128 * 128 * 128];   // pac16 out / inorm in-place  (8 MB)
__device__ float g_g1[128 * 256 * 256];   // guide lv1                   (32 MB)
__device__ float g_kk20[256 * 256 * 4];   // kk map for pac20
__device__ float g_x2[64 * 256 * 256];    // pac20 out / inorm in-place  (16 MB)

// ---------------------------------------------------------------------------
// Packed f32x2 + cp.async helpers
// ---------------------------------------------------------------------------
typedef unsigned long long u64;

__device__ __forceinline__ u64 pk2(float x, float y) {
    u64 r;
    asm("mov.b64 %0, {%1, %2};" : "=l"(r) : "f"(x), "f"(y));
    return r;
}
__device__ __forceinline__ void fma2(u64& d, u64 a, u64 b) {
    asm("fma.rn.f32x2 %0, %1, %2, %0;" : "+l"(d) : "l"(a), "l"(b));
}
__device__ __forceinline__ float2 up2(u64 v) {
    float lo, hi;
    asm("mov.b64 {%0, %1}, %2;" : "=f"(lo), "=f"(hi) : "l"(v));
    return make_float2(lo, hi);
}

__device__ __forceinline__ unsigned smem_u32(const void* p) {
    return (unsigned)__cvta_generic_to_shared(p);
}
// 4-byte async copy; ok=false -> zero-fill (src-size 0; src pre-clamped valid)
__device__ __forceinline__ void cp4(unsigned dst, const void* src, bool ok) {
    int sz = ok ? 4 : 0;
    asm volatile("cp.async.ca.shared.global [%0], [%1], 4, %2;"
                 :: "r"(dst), "l"(src), "r"(sz) : "memory");
}
#define CP_COMMIT() asm volatile("cp.async.commit_group;" ::: "memory")

// ---------------------------------------------------------------------------
// Fused double (instance-norm + residual):  y = scale*x + shift
// ---------------------------------------------------------------------------
__global__ void inorm2_kernel(const float* x, float* y, int HW) {
    int c = blockIdx.x;
    const float* xc = x + (size_t)c * HW;
    float* yc = y + (size_t)c * HW;

    float s = 0.f, s2 = 0.f;
    for (int i = threadIdx.x; i < HW; i += blockDim.x) {
        float v = xc[i];
        s += v;
        s2 = fmaf(v, v, s2);
    }
    __shared__ float rs[32], rs2[32];
    #pragma unroll
    for (int o = 16; o; o >>= 1) {
        s += __shfl_xor_sync(0xFFFFFFFFu, s, o);
        s2 += __shfl_xor_sync(0xFFFFFFFFu, s2, o);
    }
    int w = threadIdx.x >> 5, l = threadIdx.x & 31;
    if (l == 0) { rs[w] = s; rs2[w] = s2; }
    __syncthreads();
    int nw = blockDim.x >> 5;
    if (w == 0) {
        s = (l < nw) ? rs[l] : 0.f;
        s2 = (l < nw) ? rs2[l] : 0.f;
        #pragma unroll
        for (int o = 16; o; o >>= 1) {
            s += __shfl_xor_sync(0xFFFFFFFFu, s, o);
            s2 += __shfl_xor_sync(0xFFFFFFFFu, s2, o);
        }
        if (l == 0) { rs[0] = s; rs2[0] = s2; }
    }
    __syncthreads();
    float inv = 1.f / (float)HW;
    float m = rs[0] * inv;
    float v = fmaxf(rs2[0] * inv - m * m, 0.f);
    float r1 = rsqrtf(v + 1e-5f);
    float a = 1.f + r1;
    float r2 = rsqrtf(a * a * v + 1e-5f);
    float scale = a * (r2 + 1.f);
    float shift = -(a * r2 + r1) * m;
    for (int i = threadIdx.x; i < HW; i += blockDim.x)
        yc[i] = fmaf(scale, xc[i], shift);
}

// ---------------------------------------------------------------------------
// Direct 3x3 SAME conv — cp.async double-buffered channel pipeline with
// chunk-invariant prefetch addressing (div/mod hoisted out of the loop).
// Block = 128 threads (16x8). Each thread: PY x 2 output pixels, OCT channels.
// ---------------------------------------------------------------------------
template <int CC, int OCT, int PY>
__global__ __launch_bounds__(128) void conv3x3_kernel(
    const float* __restrict__ in, const float* __restrict__ w,
    const float* __restrict__ b, float* __restrict__ out,
    int Cin, int Cout, int H, int W)
{
    constexpr int TH = 8 * PY, TW = 32;
    constexpr int XN = (TH + 2) * (TW + 2);
    constexpr int NP = 2 * PY;
    constexpr int NJ = OCT / 2;
    constexpr int NWE = CC * 9 * OCT;
    constexpr int RITER = (XN + 127) / 128;
    constexpr int WITER = (NWE + 127) / 128;
    __shared__ float sIn[2][CC][TH + 2][TW + 2];
    __shared__ __align__(16) float sW[2][CC][9][OCT];

    int tx = threadIdx.x, ty = threadIdx.y;       // (16, 8)
    int tid = ty * 16 + tx;
    int x0 = blockIdx.x * TW, y0 = blockIdx.y * TH;
    int oc0 = blockIdx.z * OCT;
    int HW = H * W;

    // ---- chunk-invariant prefetch addressing (computed ONCE) ----
    int rsrc[RITER]; bool rok[RITER], rvalid[RITER];
    #pragma unroll
    for (int q = 0; q < RITER; q++) {
        int r = tid + 128 * q;
        rvalid[q] = (r < XN);
        int iy = r / (TW + 2), ix = r % (TW + 2);
        int gy = y0 + iy - 1, gx = x0 + ix - 1;
        rok[q] = rvalid[q] && gy >= 0 && gy < H && gx >= 0 && gx < W;
        int cgy = min(max(gy, 0), H - 1);
        int cgx = min(max(gx, 0), W - 1);
        rsrc[q] = cgy * W + cgx;
    }
    int wsrc[WITER]; bool wok[WITER], wvalid[WITER];
    #pragma unroll
    for (int q = 0; q < WITER; q++) {
        int idx = tid + 128 * q;
        wvalid[q] = (idx < NWE);
        int oc = idx % OCT;
        int rem = idx / OCT;
        int k = rem % 9;
        int c = rem / 9;
        int gco = oc0 + oc;
        wok[q] = wvalid[q] && (gco < Cout);
        int cg = min(gco, Cout - 1);
        wsrc[q] = (cg * Cin + c) * 9 + k;     // chunk adds cc0*9
    }
    unsigned sxb = smem_u32(&sIn[0][0][0][0]);
    unsigned swb = smem_u32(&sW[0][0][0][0]);

    u64 acc[NP][NJ];
    #pragma unroll
    for (int p = 0; p < NP; p++)
        #pragma unroll
        for (int j = 0; j < NJ; j++) acc[p][j] = 0ull;

    const int nch = Cin / CC;

    auto prefetch = [&](int chunk, int bi) {
        int cc0 = chunk * CC;
        const float* inb = in + (size_t)cc0 * HW;
        #pragma unroll
        for (int c = 0; c < CC; c++) {
            #pragma unroll
            for (int q = 0; q < RITER; q++) {
                if (rvalid[q]) {
                    int r = tid + 128 * q;
                    cp4(sxb + ((bi * CC + c) * XN + r) * 4,
                        inb + (size_t)c * HW + rsrc[q], rok[q]);
                }
            }
        }
        const float* wb2 = w + (size_t)cc0 * 9;
        #pragma unroll
        for (int q = 0; q < WITER; q++) {
            if (wvalid[q]) {
                int idx = tid + 128 * q;
                cp4(swb + (bi * NWE + idx) * 4, wb2 + wsrc[q], wok[q]);
            }
        }
        CP_COMMIT();
    };

    prefetch(0, 0);
    for (int ch = 0; ch < nch; ch++) {
        int bi = ch & 1;
        if (ch + 1 < nch) {
            prefetch(ch + 1, bi ^ 1);
            asm volatile("cp.async.wait_group 1;" ::: "memory");
        } else {
            asm volatile("cp.async.wait_group 0;" ::: "memory");
        }
        __syncthreads();

        #pragma unroll 1
        for (int c = 0; c < CC; c++) {
            u64 rp[PY + 2][4];
            #pragma unroll
            for (int r = 0; r < PY + 2; r++) {
                float2 v0 = *reinterpret_cast<const float2*>(&sIn[bi][c][PY * ty + r][2 * tx]);
                float2 v1 = *reinterpret_cast<const float2*>(&sIn[bi][c][PY * ty + r][2 * tx + 2]);
                rp[r][0] = pk2(v0.x, v0.x);
                rp[r][1] = pk2(v0.y, v0.y);
                rp[r][2] = pk2(v1.x, v1.x);
                rp[r][3] = pk2(v1.y, v1.y);
            }
            #pragma unroll
            for (int o4 = 0; o4 < OCT / 4; o4++) {
                #pragma unroll
                for (int k = 0; k < 9; k++) {
                    ulonglong2 wp = *reinterpret_cast<const ulonglong2*>(&sW[bi][c][k][o4 * 4]);
                    int ky = k / 3, kx = k % 3;
                    #pragma unroll
                    for (int py = 0; py < PY; py++) {
                        #pragma unroll
                        for (int px = 0; px < 2; px++) {
                            int p = py * 2 + px;
                            fma2(acc[p][o4 * 2 + 0], rp[py + ky][px + kx], wp.x);
                            fma2(acc[p][o4 * 2 + 1], rp[py + ky][px + kx], wp.y);
                        }
                    }
                }
            }
        }
        __syncthreads();
    }

    int gx = x0 + 2 * tx;
    #pragma unroll
    for (int j = 0; j < NJ; j++) {
        #pragma unroll
        for (int sub = 0; sub < 2; sub++) {
            int gco = oc0 + 2 * j + sub;
            if (gco >= Cout) continue;
            float bb = b[gco];
            #pragma unroll
            for (int py = 0; py < PY; py++) {
                float2 a0 = up2(acc[py * 2 + 0][j]);
                float2 a1 = up2(acc[py * 2 + 1][j]);
                float e0 = (sub ? a0.y : a0.x) + bb;
                float e1 = (sub ? a1.y : a1.x) + bb;
                int gy = y0 + PY * ty + py;
                *reinterpret_cast<float2*>(&out[(size_t)gco * HW + (size_t)gy * W + gx]) =
                    make_float2(e0, e1);
            }
        }
    }
}

// ---------------------------------------------------------------------------
// PAC kernel map: kk4[y][x][t]; channel-parallel with smem reduction.
// Invalid/boundary terms stored as 0 so the apply kernel is branch-free.
// ---------------------------------------------------------------------------
__global__ __launch_bounds__(256) void kk_kernel(
    const float* __restrict__ g, float* __restrict__ kk4,
    int Cg, int Ho, int Wo)
{
    int tx = threadIdx.x;        // 0..31 (pixel)
    int grp = threadIdx.y;       // 0..7  (channel group)
    int xo = blockIdx.x * 32 + tx;
    int y = blockIdx.y;
    int HW = Ho * Wo;
    bool yodd = (y & 1), xodd = (xo & 1);
    int i0 = yodd ? 0 : 1, i1 = yodd ? 2 : 1;
    int j0 = xodd ? 0 : 1, j1 = xodd ? 2 : 1;
    bool vi1 = yodd && (y < Ho - 1);
    bool vj1 = xodd && (xo < Wo - 1);

    int Ya[2] = { y + i0 - 1, y + i1 - 1 };
    int Xb[2] = { xo + j0 - 1, xo + j1 - 1 };
    bool ib[4];
    int off[4];
    #pragma unroll
    for (int a = 0; a < 2; a++)
        #pragma unroll
        for (int bb = 0; bb < 2; bb++) {
            int t = a * 2 + bb;
            ib[t] = (Ya[a] >= 0 && Ya[a] < Ho && Xb[bb] >= 0 && Xb[bb] < Wo);
            off[t] = Ya[a] * Wo + Xb[bb];
        }
    int base = y * Wo + xo;
    float s0 = 0.f, s1 = 0.f, s2 = 0.f, s3 = 0.f;
    for (int c = grp; c < Cg; c += 8) {
        const float* gc = g + (size_t)c * HW;
        float gv = gc[base];
        float n0 = ib[0] ? gc[off[0]] : 0.f;
        float n1 = ib[1] ? gc[off[1]] : 0.f;
        float n2 = ib[2] ? gc[off[2]] : 0.f;
        float n3 = ib[3] ? gc[off[3]] : 0.f;
        float d;
        d = n0 - gv; s0 = fmaf(d, d, s0);
        d = n1 - gv; s1 = fmaf(d, d, s1);
        d = n2 - gv; s2 = fmaf(d, d, s2);
        d = n3 - gv; s3 = fmaf(d, d, s3);
    }
    __shared__ float4 red[8][32];
    red[grp][tx] = make_float4(s0, s1, s2, s3);
    __syncthreads();
    if (grp == 0) {
        s0 = 0.f; s1 = 0.f; s2 = 0.f; s3 = 0.f;
        #pragma unroll
        for (int gidx = 0; gidx < 8; gidx++) {
            float4 v = red[gidx][tx];
            s0 += v.x; s1 += v.y; s2 += v.z; s3 += v.w;
        }
        float4 r;
        r.x = expf(-0.5f * s0);
        r.y = vj1 ? expf(-0.5f * s1) : 0.f;
        r.z = vi1 ? expf(-0.5f * s2) : 0.f;
        r.w = (vi1 && vj1) ? expf(-0.5f * s3) : 0.f;
        reinterpret_cast<float4*>(kk4)[base] = r;
    }
}

// ---------------------------------------------------------------------------
// PAC transposed conv apply — quad-parity (proven R12 compute body),
// cp.async double-buffered pipeline with chunk-invariant prefetch addressing.
//   o00: tap(1,1)·in00
//   o01: tap(1,0)·in00 + tap(1,2)·in01
//   o10: tap(0,1)·in00 + tap(2,1)·in10
//   o11: tap(0,0)·in00 + tap(0,2)·in01 + tap(2,0)·in10 + tap(2,2)·in11
// Block = 128 threads (16x8 quads) -> output tile 32x16. Weights (Ci,Co,3,3).
// ---------------------------------------------------------------------------
template <int CC, int OCT>
__global__ __launch_bounds__(128) void pac_kernel(
    const float* __restrict__ x, const float* __restrict__ kk4,
    const float* __restrict__ w, const float* __restrict__ b,
    float* __restrict__ out, int Ci, int Co, int Hin, int Ho)
{
    const int Wo = Ho;
    const int Win = Hin;
    constexpr int QX = 16, QY = 8;
    constexpr int XH = QY + 1, XW = QX + 2;
    constexpr int XN = XH * XW;
    constexpr int NJ = OCT / 2;
    constexpr int NWE = CC * 9 * OCT;
    constexpr int RITER = (XN + 127) / 128;
    constexpr int WITER = (NWE + 127) / 128;
    __shared__ float sX[2][CC][XH][XW];
    __shared__ __align__(16) float sW[2][CC][9][OCT];

    int tx = threadIdx.x, ty = threadIdx.y; // (16, 8)
    int tid = ty * 16 + tx;
    int qx0 = blockIdx.x * QX, qy0 = blockIdx.y * QY;
    int oc0 = blockIdx.z * OCT;
    int ox0 = 2 * (qx0 + tx), oy0 = 2 * (qy0 + ty);
    int HWin = Hin * Win;

    // tap t -> destination output pixel row in acc
    constexpr int row_of[9] = { 3, 2, 3, 1, 0, 1, 3, 2, 3 };

    const float4* kp4 = reinterpret_cast<const float4*>(kk4);
    float4 kq00 = kp4[(size_t)oy0 * Wo + ox0];
    float4 kq01 = kp4[(size_t)oy0 * Wo + ox0 + 1];
    float4 kq10 = kp4[(size_t)(oy0 + 1) * Wo + ox0];
    float4 kq11 = kp4[(size_t)(oy0 + 1) * Wo + ox0 + 1];
    float k11 = kq00.x;
    float k10 = kq01.x, k12 = kq01.y;
    float k01 = kq10.x, k21 = kq10.z;
    float k00 = kq11.x, k02 = kq11.y, k20 = kq11.z, k22 = kq11.w;

    // ---- chunk-invariant prefetch addressing (computed ONCE) ----
    int rsrc[RITER]; bool rok[RITER], rvalid[RITER];
    #pragma unroll
    for (int q = 0; q < RITER; q++) {
        int r = tid + 128 * q;
        rvalid[q] = (r < XN);
        int ih = r / XW, iw = r % XW;
        int gh = qy0 + ih, gw = qx0 + iw;
        rok[q] = rvalid[q] && gh < Hin && gw < Win;
        int cgh = min(gh, Hin - 1);
        int cgw = min(gw, Win - 1);
        rsrc[q] = cgh * Win + cgw;
    }
    int wsrc[WITER]; bool wok[WITER], wvalid[WITER];
    #pragma unroll
    for (int q = 0; q < WITER; q++) {
        int idx = tid + 128 * q;
        wvalid[q] = (idx < NWE);
        int oc = idx % OCT;
        int rem = idx / OCT;
        int tap = rem % 9;
        int c = rem / 9;
        int gco = oc0 + oc;
        wok[q] = wvalid[q] && (gco < Co);
        int cg = min(gco, Co - 1);
        wsrc[q] = (c * Co + cg) * 9 + tap;    // chunk adds cc0*Co*9
    }
    unsigned sxb = smem_u32(&sX[0][0][0][0]);
    unsigned swb = smem_u32(&sW[0][0][0][0]);

    u64 acc[4][NJ];  // [0]=o00 [1]=o01 [2]=o10 [3]=o11
    #pragma unroll
    for (int p = 0; p < 4; p++)
        #pragma unroll
        for (int j = 0; j < NJ; j++) acc[p][j] = 0ull;

    const int nch = Ci / CC;

    auto prefetch = [&](int chunk, int bi) {
        int cc0 = chunk * CC;
        const float* xb = x + (size_t)cc0 * HWin;
        #pragma unroll
        for (int c = 0; c < CC; c++) {
            #pragma unroll
            for (int q = 0; q < RITER; q++) {
                if (rvalid[q]) {
                    int r = tid + 128 * q;
                    cp4(sxb + ((bi * CC + c) * XN + r) * 4,
                        xb + (size_t)c * HWin + rsrc[q], rok[q]);
                }
            }
        }
        const float* wb2 = w + (size_t)cc0 * Co * 9;
        #pragma unroll
        for (int q = 0; q < WITER; q++) {
            if (wvalid[q]) {
                int idx = tid + 128 * q;
                cp4(swb + (bi * NWE + idx) * 4, wb2 + wsrc[q], wok[q]);
            }
        }
        CP_COMMIT();
    };

    prefetch(0, 0);
    for (int ch = 0; ch < nch; ch++) {
        int bi = ch & 1;
        if (ch + 1 < nch) {
            prefetch(ch + 1, bi ^ 1);
            asm volatile("cp.async.wait_group 1;" ::: "memory");
        } else {
            asm volatile("cp.async.wait_group 0;" ::: "memory");
        }
        __syncthreads();

        #pragma unroll 1
        for (int c = 0; c < CC; c++) {
            float in00 = sX[bi][c][ty][tx],     in01 = sX[bi][c][ty][tx + 1];
            float in10 = sX[bi][c][ty + 1][tx], in11 = sX[bi][c][ty + 1][tx + 1];
            float pv[9];
            pv[0] = k00 * in00;
            pv[1] = k01 * in00;
            pv[2] = k02 * in01;
            pv[3] = k10 * in00;
            pv[4] = k11 * in00;
            pv[5] = k12 * in01;
            pv[6] = k20 * in10;
            pv[7] = k21 * in10;
            pv[8] = k22 * in11;
            u64 pp[9];
            #pragma unroll
            for (int t = 0; t < 9; t++) pp[t] = pk2(pv[t], pv[t]);
            #pragma unroll
            for (int o4 = 0; o4 < OCT / 4; o4++) {
                #pragma unroll
                for (int t = 0; t < 9; t++) {
                    ulonglong2 wp = *reinterpret_cast<const ulonglong2*>(&sW[bi][c][t][o4 * 4]);
                    int p = row_of[t];
                    fma2(acc[p][o4 * 2 + 0], pp[t], wp.x);
                    fma2(acc[p][o4 * 2 + 1], pp[t], wp.y);
                }
            }
        }
        __syncthreads();
    }

    size_t HWo = (size_t)Ho * Wo;
    #pragma unroll
    for (int j = 0; j < NJ; j++) {
        #pragma unroll
        for (int sub = 0; sub < 2; sub++) {
            int gco = oc0 + 2 * j + sub;
            if (gco >= Co) continue;
            float bb = b[gco];
            float2 a0 = up2(acc[0][j]);
            float2 a1 = up2(acc[1][j]);
            float2 a2 = up2(acc[2][j]);
            float2 a3 = up2(acc[3][j]);
            *reinterpret_cast<float2*>(&out[(size_t)gco * HWo + (size_t)oy0 * Wo + ox0]) =
                make_float2((sub ? a0.y : a0.x) + bb, (sub ? a1.y : a1.x) + bb);
            *reinterpret_cast<float2*>(&out[(size_t)gco * HWo + (size_t)(oy0 + 1) * Wo + ox0]) =
                make_float2((sub ? a2.y : a2.x) + bb, (sub ? a3.y : a3.x) + bb);
        }
    }
}

// ---------------------------------------------------------------------------
// Launcher — single stream, proven grids.
// ---------------------------------------------------------------------------
extern "C" void kernel_launch(void* const* d_in, const int* in_sizes, int n_in,
                              void* d_out, int out_size)
{
    (void)in_sizes; (void)n_in; (void)out_size;
    const float* x      = (const float*)d_in[0];
    const float* ef2    = (const float*)d_in[1];
    const float* ef1    = (const float*)d_in[2];
    const float* w_adj2 = (const float*)d_in[3];
    const float* b_adj2 = (const float*)d_in[4];
    const float* w_adj1 = (const float*)d_in[5];
    const float* b_adj1 = (const float*)d_in[6];
    const float* w_p16  = (const float*)d_in[7];
    const float* b_p16  = (const float*)d_in[8];
    const float* w_p20  = (const float*)d_in[9];
    const float* b_p20  = (const float*)d_in[10];
    const float* w_o    = (const float*)d_in[11];
    const float* b_o    = (const float*)d_in[12];
    float* out = (float*)d_out;

    float *px0, *pg2, *pk16, *px1, *pg1, *pk20, *px2;
    cudaGetSymbolAddress((void**)&px0, g_x0);
    cudaGetSymbolAddress((void**)&pg2, g_g2);
    cudaGetSymbolAddress((void**)&pk16, g_kk16);
    cudaGetSymbolAddress((void**)&px1, g_x1);
    cudaGetSymbolAddress((void**)&pg1, g_g1);
    cudaGetSymbolAddress((void**)&pk20, g_kk20);
    cudaGetSymbolAddress((void**)&px2, g_x2);

    dim3 blk(16, 8);
    dim3 kblk(32, 8);

    // x = double inorm+residual (fused analytically)
    inorm2_kernel<<<256, 256>>>(x, px0, 64 * 64);

    // g2 = conv3x3(ef_lv2): 128 -> 256 @ 128x128
    conv3x3_kernel<8, 8, 2><<<dim3(4, 8, 32), blk>>>(ef2, w_adj2, b_adj2, pg2, 128, 256, 128, 128);

    // kk for pac16 (guide channels = 256, Ho = 128)
    kk_kernel<<<dim3(4, 128), kblk>>>(pg2, pk16, 256, 128, 128);

    // pac16: 256 -> 128, out 128x128  (grid 1024)
    pac_kernel<8, 4><<<dim3(4, 8, 32), blk>>>(px0, pk16, w_p16, b_p16, px1, 256, 128, 64, 128);

    // double inorm+res (in place)
    inorm2_kernel<<<128, 256>>>(px1, px1, 128 * 128);

    // g1 = conv3x3(ef_lv1): 64 -> 128 @ 256x256
    conv3x3_kernel<8, 8, 2><<<dim3(8, 16, 16), blk>>>(ef1, w_adj1, b_adj1, pg1, 64, 128, 256, 256);

    // kk for pac20 (guide channels = 128, Ho = 256)
    kk_kernel<<<dim3(8, 256), kblk>>>(pg1, pk20, 128, 256, 256);

    // pac20: 128 -> 64, out 256x256  (grid 2048)
    pac_kernel<8, 4><<<dim3(8, 16, 16), blk>>>(px1, pk20, w_p20, b_p20, px2, 128, 64, 128, 256);

    // double inorm+res (in place)
    inorm2_kernel<<<64, 256>>>(px2, px2, 256 * 256);

    // final conv: 64 -> 3 @ 256x256 straight into d_out
    conv3x3_kernel<4, 4, 1><<<dim3(8, 32, 1), blk>>>(px2, w_o, b_o, out, 64, 3, 256, 256);
}